// round 13
// baseline (speedup 1.0000x reference)
#include <cuda_runtime.h>
#include <cuda_bf16.h>
#include <stdint.h>

// RoIAlign: feat (B=4, C=256, H=200, W=304) fp32, rois (N,5) fp32
// OUT=7, SCALE=0.25, sampling_ratio=1, aligned=False
// out: (N, C, 7, 7) fp32

#define B_ 4
#define C_ 256
#define H_ 200
#define W_ 304
#define OUT_ 7
#define BINS_PER_ROI (OUT_ * OUT_)      // 49
#define HW_ (H_ * W_)                   // 60800
#define CHW_ (C_ * HW_)                 // 15,564,800
#define SCALE_ 0.25f

#define MAX_ROWS 14                     // 7 (y0,y0+1) pairs max
#define TILE_XS 57                      // x stride: max span 55, odd for banks
#define CH_PER_BLOCK 8
#define NCG_ (C_ / CH_PER_BLOCK)        // 32 channel groups
#define ELEMS_ (CH_PER_BLOCK * BINS_PER_ROI)  // 392

#define MAX_ROIS 8192
__device__ float4 g_w[MAX_ROIS * BINS_PER_ROI];     // bilinear weights * valid
__device__ int    g_toff[MAX_ROIS * BINS_PER_ROI];  // smem tap offset r0*57+xoff
__device__ int    g_rowlist[MAX_ROIS * 16];         // unique feature rows (y)
__device__ int4   g_meta[MAX_ROIS];                 // {xmin, span, nrows, b*CHW}
__device__ int    g_order[MAX_ROIS];                // rois sorted by batch

__device__ __forceinline__ int calc_y0(float sy1, float bin_h, int ph) {
    float y = sy1 + ((float)ph + 0.5f) * bin_h;
    y = fminf(fmaxf(y, 0.0f), (float)(H_ - 1));
    int y0 = (int)floorf(y);
    if (y0 >= H_ - 1) y0 = H_ - 2;
    return y0;
}
__device__ __forceinline__ int calc_x0(float sx1, float bin_w, int pw) {
    float x = sx1 + ((float)pw + 0.5f) * bin_w;
    x = fminf(fmaxf(x, 0.0f), (float)(W_ - 1));
    int x0 = (int)floorf(x);
    if (x0 >= W_ - 1) x0 = W_ - 2;
    return x0;
}

// ---------------------------------------------------------------------------
// Fused phase 1: blocks [0, gridDim-2] do per-(roi,bin) prep; last block does
// the 4-bucket batch counting sort (disjoint outputs; gather needs both).
// ---------------------------------------------------------------------------
__global__ __launch_bounds__(256)
void roi_prep_sort_kernel(const float* __restrict__ rois,
                          int n_bins, int n_rois) {
    int tid = threadIdx.x;

    if (blockIdx.x == gridDim.x - 1) {
        __shared__ int s_count[B_];
        __shared__ int s_base[B_];
        __shared__ int s_pos[B_];

        if (tid < B_) s_count[tid] = 0;
        __syncthreads();
        for (int n = tid; n < n_rois; n += 256)
            atomicAdd(&s_count[(int)rois[n * 5]], 1);
        __syncthreads();
        if (tid == 0) {
            int acc = 0;
            for (int b = 0; b < B_; b++) { s_base[b] = acc; acc += s_count[b]; s_pos[b] = 0; }
        }
        __syncthreads();
        for (int n = tid; n < n_rois; n += 256) {
            int b = (int)rois[n * 5];
            int pos = s_base[b] + atomicAdd(&s_pos[b], 1);
            g_order[pos] = n;
        }
        return;
    }

    int i = blockIdx.x * 256 + tid;
    if (i >= n_bins) return;

    int n  = i / BINS_PER_ROI;
    int p  = i - n * BINS_PER_ROI;
    int ph = p / OUT_;
    int pw = p - ph * OUT_;

    const float* r = rois + n * 5;
    int   b   = (int)r[0];
    float sx1 = r[1] * SCALE_;
    float sy1 = r[2] * SCALE_;
    float sx2 = r[3] * SCALE_;
    float sy2 = r[4] * SCALE_;

    float rw = fmaxf(sx2 - sx1, 1.0f);   // aligned=False -> clamp to 1
    float rh = fmaxf(sy2 - sy1, 1.0f);
    float bin_w = rw * (1.0f / OUT_);
    float bin_h = rh * (1.0f / OUT_);

    // ---- own sample point: weights ----
    float x = sx1 + ((float)pw + 0.5f) * bin_w;
    float y = sy1 + ((float)ph + 0.5f) * bin_h;
    float valid = (y > -1.0f && y < (float)H_ && x > -1.0f && x < (float)W_)
                      ? 1.0f : 0.0f;
    y = fminf(fmaxf(y, 0.0f), (float)(H_ - 1));
    x = fminf(fmaxf(x, 0.0f), (float)(W_ - 1));
    int   y0 = (int)floorf(y);
    int   x0 = (int)floorf(x);
    float ly = y - (float)y0;
    float lx = x - (float)x0;
    if (y0 >= H_ - 1) { y0 = H_ - 2; ly = 1.0f; }
    if (x0 >= W_ - 1) { x0 = W_ - 2; lx = 1.0f; }
    float hy = 1.0f - ly;
    float hx = 1.0f - lx;

    g_w[i] = make_float4(hy * hx * valid, hy * lx * valid,
                         ly * hx * valid, ly * lx * valid);

    // ---- row index of y0 in the roi's sorted-unique row list ----
    // List = append-unique of {y0(j), y0(j)+1} for j=0..6 (monotone in j).
    int rows[MAX_ROWS];
    int nr = 0, last = -1000000;
    #pragma unroll
    for (int j = 0; j < OUT_; j++) {
        int v = calc_y0(sy1, bin_h, j);
        if (v > last)     { rows[nr++] = v;     last = v; }
        if (v + 1 > last) { rows[nr++] = v + 1; last = v + 1; }
    }
    int r0idx = 0;
    #pragma unroll
    for (int k = 0; k < MAX_ROWS; k++)
        if (k < nr && rows[k] < y0) r0idx++;

    int xmin = calc_x0(sx1, bin_w, 0);
    g_toff[i] = r0idx * TILE_XS + (x0 - xmin);

    // ---- per-roi metadata (one thread per roi) ----
    if (p == 0) {
        int xmax0 = calc_x0(sx1, bin_w, OUT_ - 1);
        int span  = xmax0 - xmin + 2;          // covers x0..x0+1 of all bins
        for (int k = 0; k < nr; k++) g_rowlist[n * 16 + k] = rows[k];
        g_meta[n] = make_int4(xmin, span, nr, b * CHW_);
    }
}

// ---------------------------------------------------------------------------
// Phase 2: one block = (batch-sorted roi slot, 8-channel group), 256 threads.
// Warp w stages channel c0+w's needed rows into smem with COALESCED loads
// (lanes = consecutive x -> 1-2 lines per warp instruction, vs ~10 for the
// scattered per-bin taps). Compute then takes 4 taps from smem where the
// cost is conflict degree (~1-2), not line count. Base + {0,1,57,58} gives
// all 4 taps from one offset (r1 = r0+1 is guaranteed adjacent in the list).
// ---------------------------------------------------------------------------
__global__ __launch_bounds__(256)
void roi_gather_kernel(const float* __restrict__ feat,
                       float* __restrict__ out) {
    __shared__ float s_tile[CH_PER_BLOCK][MAX_ROWS * TILE_XS];  // 25.5 KB
    __shared__ int   s_rows[MAX_ROWS];

    int slot = blockIdx.x >> 5;          // / NCG_ (32)
    int cg   = blockIdx.x & (NCG_ - 1);
    int n    = g_order[slot];
    int c0   = cg * CH_PER_BLOCK;

    int tid  = threadIdx.x;
    int wid  = tid >> 5;
    int lane = tid & 31;

    int4 meta = g_meta[n];               // {xmin, span, nrows, bbase}
    if (tid < meta.z) s_rows[tid] = g_rowlist[n * 16 + tid];
    __syncthreads();

    // stage: warp w -> channel c0+w
    {
        const float* src = feat + meta.w + (c0 + wid) * HW_ + meta.x;
        float* dst = s_tile[wid];
        for (int rr = 0; rr < meta.z; rr++) {
            const float* rowp = src + s_rows[rr] * W_;
            for (int xx = lane; xx < meta.y; xx += 32)
                dst[rr * TILE_XS + xx] = __ldg(rowp + xx);
        }
    }
    __syncthreads();

    // compute 392 elems; stores contiguous (e is the output offset)
    float* out_base = out + (n * C_ + c0) * BINS_PER_ROI;
    const float4* wbase = g_w + n * BINS_PER_ROI;
    const int*    tbase = g_toff + n * BINS_PER_ROI;

    #pragma unroll
    for (int e = tid; e < ELEMS_; e += 256) {
        int c = e / BINS_PER_ROI;
        int p = e - c * BINS_PER_ROI;

        float4 w    = __ldg(wbase + p);
        int    toff = __ldg(tbase + p);

        const float* tp = s_tile[c] + toff;
        out_base[e] = tp[0] * w.x + tp[1] * w.y
                    + tp[TILE_XS] * w.z + tp[TILE_XS + 1] * w.w;
    }
}

// ---------------------------------------------------------------------------
extern "C" void kernel_launch(void* const* d_in, const int* in_sizes, int n_in,
                              void* d_out, int out_size) {
    const float* feat = (const float*)d_in[0];
    const float* rois = (const float*)d_in[1];
    float* out = (float*)d_out;

    int N = in_sizes[1] / 5;
    int n_bins = N * BINS_PER_ROI;
    int prep_blocks = (n_bins + 255) / 256;

    roi_prep_sort_kernel<<<prep_blocks + 1, 256>>>(rois, n_bins, N);
    roi_gather_kernel<<<N * NCG_, 256>>>(feat, out);
}